// round 12
// baseline (speedup 1.0000x reference)
#include <cuda_runtime.h>
#include <cuda_fp16.h>
#include <cstdint>

#define N_NODES 50000
#define DS 127
#define DPAD 128
#define NE 800000
#define EPSF 1e-7f
#define GR 64       // rows per gemm block
#define HSTRIDE 136 // smem stride in halves (conflict-free ldmatrix)

// g_x16: x as fp16, padded [N][128], pad col 0
// g_h16: h1 = relu(agg1)+x as fp16 (layer-2 prologue), pad col 0
// g_z  : gemm output fp16; pad col 0
// g_agg: fp16 atomic accumulation target; pad col garbage, never read
// g_Wt : W1,W2 as fp16, n-major [n][k] 128x128 each, pads zero
__device__ __align__(16) __half g_x16[N_NODES * DPAD];
__device__ __align__(16) __half g_h16[N_NODES * DPAD];
__device__ __align__(16) __half g_z[N_NODES * DPAD];
__device__ __align__(16) __half g_agg[N_NODES * DPAD];
__device__ __align__(16) __half g_Wt[2 * DPAD * DPAD];

__device__ __forceinline__ float warp_sum(float v) {
#pragma unroll
    for (int o = 16; o; o >>= 1) v += __shfl_xor_sync(0xffffffffu, v, o);
    return v;
}

__device__ __forceinline__ void ldsm4(uint32_t* r, uint32_t addr) {
    asm volatile("ldmatrix.sync.aligned.m8n8.x4.shared.b16 {%0,%1,%2,%3}, [%4];"
                 : "=r"(r[0]), "=r"(r[1]), "=r"(r[2]), "=r"(r[3]) : "r"(addr));
}

__device__ __forceinline__ void mma16816(float* c, const uint32_t* a,
                                         uint32_t b0, uint32_t b1) {
    asm volatile(
        "mma.sync.aligned.m16n8k16.row.col.f32.f16.f16.f32 "
        "{%0,%1,%2,%3}, {%4,%5,%6,%7}, {%8,%9}, {%0,%1,%2,%3};"
        : "+f"(c[0]), "+f"(c[1]), "+f"(c[2]), "+f"(c[3])
        : "r"(a[0]), "r"(a[1]), "r"(a[2]), "r"(a[3]), "r"(b0), "r"(b1));
}

// g_Wt[l][n*128+k] = fp16(W_l[k*127+n]); zero pads
__global__ void k_prepW(const float* __restrict__ W1, const float* __restrict__ W2) {
    int idx = blockIdx.x * 256 + threadIdx.x;
    if (idx >= 2 * DPAD * DPAD) return;
    int l = idx >> 14, rem = idx & 16383, n = rem >> 7, k = rem & 127;
    const float* W = l ? W2 : W1;
    float v = (k < DS && n < DS) ? W[k * DS + n] : 0.f;
    g_Wt[idx] = __float2half(v);
}

// g_x16[row*128+c] = fp16(x[row*127+c]); pad col 0
__global__ void k_prepX(const float* __restrict__ x) {
    int idx = blockIdx.x * 256 + threadIdx.x;
    if (idx >= N_NODES * DPAD) return;
    int row = idx >> 7, c = idx & 127;
    g_x16[idx] = __float2half((c < DS) ? x[row * DS + c] : 0.f);
}

// z = half(h @ W + b) via HMMA; agg zeroed in epilogue.
// layer==0: h = x16.  layer==1: h = relu(agg) + x16 (== h1), stored fp16 to g_h16.
// 256 threads = 8 warps: warp (wm=wid>>2, wn=wid&3) = rows [wm*32,+32) x cols [wn*32,+32).
__global__ void __launch_bounds__(256, 3)
k_gemm(const float* __restrict__ b, int layer) {
    extern __shared__ __align__(16) char smem_raw[];
    __half* Wt  = (__half*)smem_raw;                 // [128][136]
    __half* Ht  = Wt + DPAD * HSTRIDE;               // [64][136]
    float*  b_s = (float*)(Ht + GR * HSTRIDE);       // [128]
    int tid  = threadIdx.x;
    int row0 = blockIdx.x * GR;

    // Wt smem fill: 2048 x 16B chunks
    {
        const uint4* src = (const uint4*)(g_Wt + layer * DPAD * DPAD);
        for (int j = tid; j < 2048; j += 256) {
            int n = j >> 4, kc = j & 15;
            *(uint4*)(Wt + n * HSTRIDE + kc * 8) = src[j];
        }
    }
    if (tid < DPAD) b_s[tid] = (tid < DS) ? b[tid] : 0.f;

    // h tile fp16: 64 rows x 16 uint4 chunks (8 halves each)
    for (int j = tid; j < GR * 16; j += 256) {
        int r = j >> 4, ch = j & 15;
        int row = row0 + r;
        uint4 v = make_uint4(0u, 0u, 0u, 0u);
        if (row < N_NODES) {
            v = ((const uint4*)(g_x16 + (size_t)row * DPAD))[ch];
            if (layer) {
                uint4 a = ((const uint4*)(g_agg + (size_t)row * DPAD))[ch];
                __half2* vh = (__half2*)&v;
                __half2* ah = (__half2*)&a;
#pragma unroll
                for (int i = 0; i < 4; i++) {
                    float2 xf = __half22float2(vh[i]);
                    float2 af = __half22float2(ah[i]);
                    vh[i] = __floats2half2_rn(xf.x + fmaxf(af.x, 0.f),
                                              xf.y + fmaxf(af.y, 0.f));
                }
                ((uint4*)(g_h16 + (size_t)row * DPAD))[ch] = v;
            }
        }
        *(uint4*)(Ht + r * HSTRIDE + ch * 8) = v;
    }
    __syncthreads();

    int lane = tid & 31, wid = tid >> 5;
    int wm = wid >> 2, wn = wid & 3;

    uint32_t ht_s = (uint32_t)__cvta_generic_to_shared(Ht);
    uint32_t wt_s = (uint32_t)__cvta_generic_to_shared(Wt);
    uint32_t aaddr[2];
#pragma unroll
    for (int mt = 0; mt < 2; mt++) {
        int rowA = wm * 32 + mt * 16 + (lane & 15);
        int kA   = (lane >> 4) * 8;
        aaddr[mt] = ht_s + (uint32_t)(rowA * HSTRIDE + kA) * 2;
    }
    uint32_t baddr[2];
#pragma unroll
    for (int p = 0; p < 2; p++) {
        int rowB = wn * 32 + p * 16 + (lane >> 4) * 8 + (lane & 7);
        int kB   = ((lane >> 3) & 1) * 8;
        baddr[p] = wt_s + (uint32_t)(rowB * HSTRIDE + kB) * 2;
    }

    float c[2][4][4];
#pragma unroll
    for (int mt = 0; mt < 2; mt++)
#pragma unroll
        for (int nt = 0; nt < 4; nt++)
#pragma unroll
            for (int j = 0; j < 4; j++) c[mt][nt][j] = 0.f;

#pragma unroll
    for (int ks = 0; ks < 8; ks++) {
        uint32_t kb = (uint32_t)(ks * 16 * 2);
        uint32_t a[2][4], bq[2][4];
        ldsm4(a[0], aaddr[0] + kb);
        ldsm4(a[1], aaddr[1] + kb);
        ldsm4(bq[0], baddr[0] + kb);
        ldsm4(bq[1], baddr[1] + kb);
#pragma unroll
        for (int mt = 0; mt < 2; mt++)
#pragma unroll
            for (int nt = 0; nt < 4; nt++)
                mma16816(c[mt][nt], a[mt], bq[nt >> 1][(nt & 1) * 2],
                         bq[nt >> 1][(nt & 1) * 2 + 1]);
    }

    // epilogue: z = half(acc + bias); zero agg
    int r_in = lane >> 2, col_in = 2 * (lane & 3);
#pragma unroll
    for (int mt = 0; mt < 2; mt++) {
#pragma unroll
        for (int nt = 0; nt < 4; nt++) {
            int row = row0 + wm * 32 + mt * 16 + r_in;
            int col = wn * 32 + nt * 8 + col_in;
            float bb0 = b_s[col], bb1 = b_s[col + 1];
            if (row < N_NODES)
                *(__half2*)(g_z + (size_t)row * DPAD + col) =
                    __floats2half2_rn(c[mt][nt][0] + bb0, c[mt][nt][1] + bb1);
            if (row + 8 < N_NODES)
                *(__half2*)(g_z + (size_t)(row + 8) * DPAD + col) =
                    __floats2half2_rn(c[mt][nt][2] + bb0, c[mt][nt][3] + bb1);
        }
    }
    {
        uint4 zz = make_uint4(0u, 0u, 0u, 0u);
        uint4* a4 = (uint4*)(g_agg + (size_t)row0 * DPAD);
        for (int j = tid; j < GR * 16; j += 256) {
            int row = row0 + (j >> 4);
            if (row < N_NODES) a4[j] = zz;
        }
    }
}

// Warp processes 16 edges, 2 at a time: lanes 0-15 = edge 2i, lanes 16-31 = edge 2i+1.
// Each 16-lane group covers one 256B row with uint4 (16B) chunks; reductions use
// red.global.add.noftz.v4.f16x2 (16B) -> half the LDG/RED/shuffle issue of v2.
// NE % 16 == 0, grid sized exactly -> no bounds checks.
__global__ void k_edge(const int* __restrict__ src, const int* __restrict__ dst,
                       const float* __restrict__ wt) {
    int warp = (blockIdx.x * blockDim.x + threadIdx.x) >> 5;
    int lane = threadIdx.x & 31;
    int e0 = warp * 16;
    int sub = lane >> 4;     // which of the 2 concurrent edges
    int l16 = lane & 15;     // 16B chunk within the row

    int s = 0, d = 0;
    float w = 0.f;
    if (lane < 16) {
        s = src[e0 + lane];
        d = dst[e0 + lane];
        w = wt[e0 + lane];
    }

    const uint4* z4 = (const uint4*)g_z;   // 16 chunks of 8 halves per row
    uint4 v[8];
#pragma unroll
    for (int i = 0; i < 8; i++) {
        int si = __shfl_sync(0xffffffffu, s, 2 * i + sub);
        v[i] = z4[(size_t)si * 16 + l16];
    }
#pragma unroll
    for (int i = 0; i < 8; i++) {
        int   di = __shfl_sync(0xffffffffu, d, 2 * i + sub);
        float wi = __shfl_sync(0xffffffffu, w, 2 * i + sub);
        __half2* vh = (__half2*)&v[i];
        uint32_t m[4];
#pragma unroll
        for (int j = 0; j < 4; j++) {
            float2 f = __half22float2(vh[j]);
            __half2 mm = __floats2half2_rn(f.x * wi, f.y * wi);
            m[j] = *(uint32_t*)&mm;
        }
        __half* a = g_agg + (size_t)di * DPAD + 8 * l16;
        asm volatile("red.global.add.noftz.v4.f16x2 [%0], {%1,%2,%3,%4};"
                     :: "l"(a), "r"(m[0]), "r"(m[1]), "r"(m[2]), "r"(m[3])
                     : "memory");
    }
}

// h2 = relu(agg2) + h1;  out = expmap0(h2)
__global__ void k_final(float* __restrict__ out) {
    int warp = (blockIdx.x * blockDim.x + threadIdx.x) >> 5;
    int lane = threadIdx.x & 31;
    if (warp >= N_NODES) return;
    float v[4];
    float n2 = 0.f;
#pragma unroll
    for (int j = 0; j < 4; j++) {
        int c = lane + 32 * j;
        float a  = __half2float(g_agg[warp * DPAD + c]);
        float hv = __half2float(g_h16[warp * DPAD + c]);
        v[j] = (c < DS) ? (fmaxf(a, 0.f) + hv) : 0.f;
        n2 += v[j] * v[j];
    }
    n2 = warp_sum(n2);
    float n = fmaxf(sqrtf(n2), EPSF);
    float t = coshf(n);
    float f = sinhf(n) / n;
    if (lane == 0) out[warp * DPAD] = t;
#pragma unroll
    for (int j = 0; j < 4; j++) {
        int c = lane + 32 * j;
        if (c < DS) out[warp * DPAD + 1 + c] = f * v[j];
    }
}

extern "C" void kernel_launch(void* const* d_in, const int* in_sizes, int n_in,
                              void* d_out, int out_size) {
    const float* x  = (const float*)d_in[0];
    const float* W1 = (const float*)d_in[1];
    const float* b1 = (const float*)d_in[2];
    const float* W2 = (const float*)d_in[3];
    const float* b2 = (const float*)d_in[4];
    const int*   es = (const int*)d_in[5];
    const int*   ed = (const int*)d_in[6];
    const float* ew = (const float*)d_in[7];
    float* out = (float*)d_out;

    const int smem_bytes = (DPAD * HSTRIDE + GR * HSTRIDE) * 2 + DPAD * 4;  // 52736
    cudaFuncSetAttribute(k_gemm, cudaFuncAttributeMaxDynamicSharedMemorySize, smem_bytes);

    int gemm_blocks = (N_NODES + GR - 1) / GR;       // 782
    int edge_blocks = (NE / 16) / 8;                 // 6250 (8 warps/block, 16 edges/warp)
    int row_blocks  = (N_NODES * 32 + 255) / 256;    // 6250

    k_prepW<<<(2 * DPAD * DPAD + 255) / 256, 256>>>(W1, W2);
    k_prepX<<<(N_NODES * DPAD + 255) / 256, 256>>>(x);

    k_gemm<<<gemm_blocks, 256, smem_bytes>>>(b1, 0);
    k_edge<<<edge_blocks, 256>>>(es, ed, ew);

    k_gemm<<<gemm_blocks, 256, smem_bytes>>>(b2, 1);
    k_edge<<<edge_blocks, 256>>>(es, ed, ew);

    k_final<<<row_blocks, 256>>>(out);
}